// round 4
// baseline (speedup 1.0000x reference)
#include <cuda_runtime.h>
#include <cuda_bf16.h>
#include <cstdint>

// Problem constants
#define VV 10000
#define BB 4096
#define SS 64
#define EE 128
#define HH 256
#define CC 18

#define BM 32      // batch rows per rnn block
#define NTHREADS 256

// Scratch (allocation-free rule: static __device__ arrays)
__device__ float g_embw[VV * HH];      // embW[v][h] = b_ih + emb[v] @ W_ih^T  (10.24 MB)
__device__ float g_whhT[HH * HH];      // W_hh transposed: [k][c]              (256 KB)
__device__ float g_last[BB * HH];      // final hidden per row                 (4 MB)

__device__ __forceinline__ float fast_tanh(float x) {
    // 1 - 2/(e^{2x}+1): correct at both saturations (e->inf => 1, e->0 => -1)
    float e = __expf(2.0f * x);
    return 1.0f - 2.0f / (e + 1.0f);
}

// ---------------------------------------------------------------------------
// Kernel 0: transpose W_hh (256x256) -> g_whhT[k][c] = W_hh[c][k]
// grid 64, 256 threads (32x32 tiles, 32x8 thread layout)
// ---------------------------------------------------------------------------
__global__ __launch_bounds__(NTHREADS) void transpose_whh_kernel(const float* __restrict__ W)
{
    __shared__ float tile[32][33];
    const int bx = blockIdx.x & 7;        // column tile
    const int by = blockIdx.x >> 3;       // row tile
    const int lx = threadIdx.x & 31;
    const int ly = threadIdx.x >> 5;      // 0..7
#pragma unroll
    for (int q = 0; q < 32; q += 8)
        tile[ly + q][lx] = W[(by * 32 + ly + q) * HH + bx * 32 + lx];
    __syncthreads();
#pragma unroll
    for (int q = 0; q < 32; q += 8)
        g_whhT[(bx * 32 + ly + q) * HH + by * 32 + lx] = tile[lx][ly + q];
}

// ---------------------------------------------------------------------------
// Kernel 1: embW[v][h] = b_ih[h] + sum_e emb[v][e] * W_ih[h][e]
// grid ceil(V/32)=313, 256 threads, 4x8 micro-tile
// ---------------------------------------------------------------------------
__global__ __launch_bounds__(NTHREADS) void embw_kernel(
    const float* __restrict__ emb,
    const float* __restrict__ W_ih,
    const float* __restrict__ b_ih)
{
    __shared__ float Asm[BM][EE];   // 32 emb rows (16 KB)
    __shared__ float Wt[16][HH];    // W_ih k-tile transposed (16 KB)

    const int b0  = blockIdx.x * BM;
    const int tid = threadIdx.x;

    // stage 32 emb rows (clamped for tail block)
    {
        const int r   = tid >> 3;
        const int seg = tid & 7;
        int v = b0 + r; if (v >= VV) v = VV - 1;
        const float4* src = reinterpret_cast<const float4*>(emb + (size_t)v * EE + seg * 16);
        float4* dst = reinterpret_cast<float4*>(&Asm[r][seg * 16]);
#pragma unroll
        for (int q = 0; q < 4; q++) dst[q] = src[q];
    }

    const int r_t = tid >> 5;
    const int c_t = tid & 31;

    float acc[4][8];
    {
        float4 bl = *reinterpret_cast<const float4*>(b_ih + c_t * 8);
        float4 bh = *reinterpret_cast<const float4*>(b_ih + c_t * 8 + 4);
        float bias[8] = {bl.x, bl.y, bl.z, bl.w, bh.x, bh.y, bh.z, bh.w};
#pragma unroll
        for (int i = 0; i < 4; i++)
#pragma unroll
            for (int j = 0; j < 8; j++) acc[i][j] = bias[j];
    }

    const int kk4   = tid & 3;
    const int cbase = tid >> 2;

    for (int k0 = 0; k0 < EE; k0 += 16) {
        __syncthreads();
#pragma unroll
        for (int q = 0; q < 4; q++) {
            const int c = cbase + 64 * q;
            float4 v = *reinterpret_cast<const float4*>(W_ih + (size_t)c * EE + k0 + kk4 * 4);
            Wt[kk4 * 4 + 0][c] = v.x;
            Wt[kk4 * 4 + 1][c] = v.y;
            Wt[kk4 * 4 + 2][c] = v.z;
            Wt[kk4 * 4 + 3][c] = v.w;
        }
        __syncthreads();
#pragma unroll
        for (int kk = 0; kk < 16; kk++) {
            float a[4];
#pragma unroll
            for (int i = 0; i < 4; i++) a[i] = Asm[r_t * 4 + i][k0 + kk];
            float w[8];
            *reinterpret_cast<float4*>(w)     = *reinterpret_cast<const float4*>(&Wt[kk][c_t * 8]);
            *reinterpret_cast<float4*>(w + 4) = *reinterpret_cast<const float4*>(&Wt[kk][c_t * 8 + 4]);
#pragma unroll
            for (int i = 0; i < 4; i++)
#pragma unroll
                for (int j = 0; j < 8; j++) acc[i][j] += a[i] * w[j];
        }
    }

#pragma unroll
    for (int i = 0; i < 4; i++) {
        const int v = b0 + r_t * 4 + i;
        if (v < VV) {
            float* dst = g_embw + (size_t)v * HH + c_t * 8;
            *reinterpret_cast<float4*>(dst)     = *reinterpret_cast<float4*>(&acc[i][0]);
            *reinterpret_cast<float4*>(dst + 4) = *reinterpret_cast<float4*>(&acc[i][4]);
        }
    }
}

// ---------------------------------------------------------------------------
// Kernel 2: RNN scan. Each block owns 32 batch rows for all 64 steps.
// h_new = tanh(embW[x_in[b][t]] + h @ W_hh^T + b_hh); save h at t == len-1.
// grid 128, 256 threads, 8x4 micro-tile, KT=32 double-buffered tiles.
// Dynamic SMEM: Hs[32*256] + Wt[2*32*256] = 96 KB
// ---------------------------------------------------------------------------
__global__ __launch_bounds__(NTHREADS) void rnn_kernel(
    const int* __restrict__ x_in,
    const int* __restrict__ x_lengths,
    const float* __restrict__ b_hh)
{
    extern __shared__ float smem[];
    float* Hs = smem;                 // [32][256]
    float* Wt = smem + BM * HH;       // [2][32][256]

    const int b0   = blockIdx.x * BM;
    const int tid  = threadIdx.x;
    const int r0   = (tid >> 6) * 8;        // 8 rows per thread
    const int col0 = (tid & 63) * 4;        // 4 cols per thread

    // zero h0
    for (int i = tid; i < BM * HH; i += NTHREADS) Hs[i] = 0.0f;

    float4 bb = *reinterpret_cast<const float4*>(b_hh + col0);
    int rl[8];
#pragma unroll
    for (int i = 0; i < 8; i++) rl[i] = x_lengths[b0 + r0 + i];

    // preload W tile 0 into buffer 0 (tile j always lives in buffer j&1)
    {
#pragma unroll
        for (int p = 0; p < 8; p++) {
            const int f4 = tid + NTHREADS * p;
            float4 v = *reinterpret_cast<const float4*>(
                g_whhT + (size_t)((f4 >> 6) * HH) + (f4 & 63) * 4);
            *reinterpret_cast<float4*>(Wt + (f4 >> 6) * HH + (f4 & 63) * 4) = v;
        }
    }
    __syncthreads();

    for (int t = 0; t < SS; t++) {
        // acc init = gathered input projection (includes b_ih)
        float acc[8][4];
#pragma unroll
        for (int i = 0; i < 8; i++) {
            const int idx = x_in[(b0 + r0 + i) * SS + t];
            float4 v = *reinterpret_cast<const float4*>(g_embw + (size_t)idx * HH + col0);
            acc[i][0] = v.x; acc[i][1] = v.y; acc[i][2] = v.z; acc[i][3] = v.w;
        }

#pragma unroll
        for (int j = 0; j < 8; j++) {              // 8 tiles of KT=32
            const int buf = j & 1;
            const int jn  = (j + 1) & 7;           // cyclic: tile 7 prefetches tile 0

            // register-staged prefetch of next tile
            float4 ld[8];
#pragma unroll
            for (int p = 0; p < 8; p++) {
                const int f4 = tid + NTHREADS * p;
                ld[p] = *reinterpret_cast<const float4*>(
                    g_whhT + (size_t)((jn * 32 + (f4 >> 6)) * HH) + (f4 & 63) * 4);
            }

            // compute tile j
            const float* Wb = Wt + buf * (32 * HH);
#pragma unroll
            for (int kc = 0; kc < 8; kc++) {       // chunks of 4 k
                float a[8][4];
#pragma unroll
                for (int i = 0; i < 8; i++)
                    *reinterpret_cast<float4*>(a[i]) = *reinterpret_cast<const float4*>(
                        Hs + (r0 + i) * HH + j * 32 + kc * 4);
                float w[4][4];
#pragma unroll
                for (int m = 0; m < 4; m++)
                    *reinterpret_cast<float4*>(w[m]) = *reinterpret_cast<const float4*>(
                        Wb + (kc * 4 + m) * HH + col0);
#pragma unroll
                for (int i = 0; i < 8; i++)
#pragma unroll
                    for (int m = 0; m < 4; m++)
#pragma unroll
                        for (int c = 0; c < 4; c++)
                            acc[i][c] += a[i][m] * w[m][c];
            }

            // store prefetched tile into the other buffer
            float* Wd = Wt + (buf ^ 1) * (32 * HH);
#pragma unroll
            for (int p = 0; p < 8; p++) {
                const int f4 = tid + NTHREADS * p;
                *reinterpret_cast<float4*>(Wd + (f4 >> 6) * HH + (f4 & 63) * 4) = ld[p];
            }
            __syncthreads();
        }

        // h update
#pragma unroll
        for (int i = 0; i < 8; i++) {
            float4 hv;
            hv.x = fast_tanh(acc[i][0] + bb.x);
            hv.y = fast_tanh(acc[i][1] + bb.y);
            hv.z = fast_tanh(acc[i][2] + bb.z);
            hv.w = fast_tanh(acc[i][3] + bb.w);
            *reinterpret_cast<float4*>(Hs + (r0 + i) * HH + col0) = hv;
            if (t == rl[i] - 1)
                *reinterpret_cast<float4*>(g_last + (size_t)(b0 + r0 + i) * HH + col0) = hv;
        }
        __syncthreads();
    }
}

// ---------------------------------------------------------------------------
// Kernel 3: out = relu(last @ W1^T + b1) @ W2^T + b2
// grid 128, 256 threads
// ---------------------------------------------------------------------------
__global__ __launch_bounds__(NTHREADS) void fc_kernel(
    const float* __restrict__ W1,
    const float* __restrict__ b1,
    const float* __restrict__ W2,
    const float* __restrict__ b2,
    float* __restrict__ out)
{
    __shared__ float Asm[BM][HH];
    __shared__ float Wt[16][HH];

    const int b0  = blockIdx.x * BM;
    const int tid = threadIdx.x;
    const int r_t = tid >> 5;
    const int c_t = tid & 31;

    for (int i = tid; i < BM * HH; i += NTHREADS)
        (&Asm[0][0])[i] = g_last[(size_t)b0 * HH + i];

    float acc[4][8];
    {
        float4 bl = *reinterpret_cast<const float4*>(b1 + c_t * 8);
        float4 bh = *reinterpret_cast<const float4*>(b1 + c_t * 8 + 4);
        float bias[8] = {bl.x, bl.y, bl.z, bl.w, bh.x, bh.y, bh.z, bh.w};
#pragma unroll
        for (int i = 0; i < 4; i++)
#pragma unroll
            for (int j = 0; j < 8; j++) acc[i][j] = bias[j];
    }

    const int kk4   = tid & 3;
    const int cbase = tid >> 2;

    for (int k0 = 0; k0 < HH; k0 += 16) {
        __syncthreads();
#pragma unroll
        for (int q = 0; q < 4; q++) {
            const int c = cbase + 64 * q;
            float4 v = *reinterpret_cast<const float4*>(W1 + (size_t)c * HH + k0 + kk4 * 4);
            Wt[kk4 * 4 + 0][c] = v.x;
            Wt[kk4 * 4 + 1][c] = v.y;
            Wt[kk4 * 4 + 2][c] = v.z;
            Wt[kk4 * 4 + 3][c] = v.w;
        }
        __syncthreads();
#pragma unroll
        for (int kk = 0; kk < 16; kk++) {
            float a[4];
#pragma unroll
            for (int i = 0; i < 4; i++) a[i] = Asm[r_t * 4 + i][k0 + kk];
            float w[8];
            *reinterpret_cast<float4*>(w)     = *reinterpret_cast<const float4*>(&Wt[kk][c_t * 8]);
            *reinterpret_cast<float4*>(w + 4) = *reinterpret_cast<const float4*>(&Wt[kk][c_t * 8 + 4]);
#pragma unroll
            for (int i = 0; i < 4; i++)
#pragma unroll
                for (int j = 0; j < 8; j++) acc[i][j] += a[i] * w[j];
        }
    }
    __syncthreads();

#pragma unroll
    for (int i = 0; i < 4; i++) {
        float yv[8];
#pragma unroll
        for (int j = 0; j < 8; j++) yv[j] = fmaxf(acc[i][j], 0.0f);
        float* yd = &Asm[r_t * 4 + i][c_t * 8];
        *reinterpret_cast<float4*>(yd)     = *reinterpret_cast<float4*>(&yv[0]);
        *reinterpret_cast<float4*>(yd + 4) = *reinterpret_cast<float4*>(&yv[4]);
    }
    __syncthreads();

    for (int e = tid; e < BM * CC; e += NTHREADS) {
        const int r = e / CC;
        const int c = e % CC;
        const float4* yv = reinterpret_cast<const float4*>(&Asm[r][0]);
        const float4* wv = reinterpret_cast<const float4*>(W2 + (size_t)c * HH);
        float s = b2[c];
#pragma unroll 8
        for (int k = 0; k < HH / 4; k++) {
            float4 a = yv[k];
            float4 w = wv[k];
            s += a.x * w.x + a.y * w.y + a.z * w.z + a.w * w.w;
        }
        out[(size_t)(b0 + r) * CC + c] = s;
    }
}

// ---------------------------------------------------------------------------
extern "C" void kernel_launch(void* const* d_in, const int* in_sizes, int n_in,
                              void* d_out, int out_size)
{
    const int*   x_in  = (const int*)  d_in[0];
    const int*   x_len = (const int*)  d_in[1];
    const float* emb   = (const float*)d_in[2];
    const float* W_ih  = (const float*)d_in[3];
    const float* W_hh  = (const float*)d_in[4];
    const float* b_ih  = (const float*)d_in[5];
    const float* b_hh  = (const float*)d_in[6];
    const float* W1    = (const float*)d_in[7];
    const float* b1    = (const float*)d_in[8];
    const float* W2    = (const float*)d_in[9];
    const float* b2    = (const float*)d_in[10];
    float* out = (float*)d_out;

    // opt-in to 96 KB dynamic SMEM for the scan kernel (idempotent)
    cudaFuncSetAttribute(rnn_kernel, cudaFuncAttributeMaxDynamicSharedMemorySize,
                         (BM * HH + 2 * 32 * HH) * (int)sizeof(float));

    transpose_whh_kernel<<<64, NTHREADS>>>(W_hh);
    embw_kernel<<<(VV + BM - 1) / BM, NTHREADS>>>(emb, W_ih, b_ih);
    rnn_kernel<<<BB / BM, NTHREADS, (BM * HH + 2 * 32 * HH) * sizeof(float)>>>(x_in, x_len, b_hh);
    fc_kernel<<<BB / BM, NTHREADS>>>(W1, b1, W2, b2, out);
}

// round 7
// speedup vs baseline: 2.6703x; 2.6703x over previous
#include <cuda_runtime.h>
#include <cuda_bf16.h>
#include <cstdint>

#define VV 10000
#define BB 4096
#define SS 64
#define EE 128
#define HH 256
#define CC 18
#define NTHREADS 256

__device__ __align__(16) float    g_embw[VV * HH];
__device__ __align__(16) float    g_last[BB * HH];
__device__ __align__(16) uint16_t g_whi16[HH * HH];   // W_hh bf16-hi, swizzled SMEM image
__device__ __align__(16) uint32_t g_wlo32[HH * HH/2]; // W_hh bf16-lo, [n][k/2] packed words

__device__ __forceinline__ float fast_tanh(float x) {
    float e = __expf(2.0f * x);
    return 1.0f - __fdividef(2.0f, e + 1.0f);
}
__device__ __forceinline__ uint32_t smem_u32(const void* p) {
    uint32_t a;
    asm("{ .reg .u64 t; cvta.to.shared.u64 t, %1; cvt.u32.u64 %0, t; }" : "=r"(a) : "l"(p));
    return a;
}
__device__ __forceinline__ void ldm4(uint32_t* d, uint32_t a) {
    asm volatile("ldmatrix.sync.aligned.m8n8.x4.shared.b16 {%0,%1,%2,%3}, [%4];"
                 : "=r"(d[0]), "=r"(d[1]), "=r"(d[2]), "=r"(d[3]) : "r"(a));
}
__device__ __forceinline__ void mma16816(float* c, const uint32_t* a, uint32_t b0, uint32_t b1) {
    asm volatile("mma.sync.aligned.m16n8k16.row.col.f32.bf16.bf16.f32 "
                 "{%0,%1,%2,%3}, {%4,%5,%6,%7}, {%8,%9}, {%0,%1,%2,%3};"
                 : "+f"(c[0]), "+f"(c[1]), "+f"(c[2]), "+f"(c[3])
                 : "r"(a[0]), "r"(a[1]), "r"(a[2]), "r"(a[3]), "r"(b0), "r"(b1));
}

// ---------------------------------------------------------------------------
// Prep: W -> bf16 hi (swizzled) + lo (plain packed)
// ---------------------------------------------------------------------------
__global__ __launch_bounds__(NTHREADS) void prep_w_kernel(const float* __restrict__ W)
{
    const int i = blockIdx.x * NTHREADS + threadIdx.x;    // 0..65535
    const int n = i >> 8, k = i & 255;
    const float w = W[i];
    __nv_bfloat16 h = __float2bfloat16(w);
    __nv_bfloat16 l = __float2bfloat16(w - __bfloat162float(h));
    g_whi16[n * 256 + (k ^ ((n & 7) << 3))] = *reinterpret_cast<uint16_t*>(&h);
    uint16_t lb = *reinterpret_cast<uint16_t*>(&l);
    // pack lo pairs: write 16-bit halves via atomic-free per-thread uint16 view
    reinterpret_cast<uint16_t*>(g_wlo32)[n * 256 + k] = lb;
}

// ---------------------------------------------------------------------------
// embW[v][h] = b_ih[h]+b_hh[h]+sum_e emb[v][e]*W_ih[h][e]
// ---------------------------------------------------------------------------
__global__ __launch_bounds__(NTHREADS) void embw_kernel(
    const float* __restrict__ emb, const float* __restrict__ W_ih,
    const float* __restrict__ b_ih, const float* __restrict__ b_hh)
{
    __shared__ float Asm[32][EE];
    __shared__ float Wt[16][HH];
    const int b0 = blockIdx.x * 32;
    const int tid = threadIdx.x;
    {
        const int r = tid >> 3, seg = tid & 7;
        int v = b0 + r; if (v >= VV) v = VV - 1;
        const float4* src = reinterpret_cast<const float4*>(emb + (size_t)v * EE + seg * 16);
        float4* dst = reinterpret_cast<float4*>(&Asm[r][seg * 16]);
#pragma unroll
        for (int q = 0; q < 4; q++) dst[q] = src[q];
    }
    const int r_t = tid >> 5, c_t = tid & 31;
    float acc[4][8];
    {
        float bias[8];
#pragma unroll
        for (int j = 0; j < 8; j++) bias[j] = b_ih[c_t * 8 + j] + b_hh[c_t * 8 + j];
#pragma unroll
        for (int i = 0; i < 4; i++)
#pragma unroll
            for (int j = 0; j < 8; j++) acc[i][j] = bias[j];
    }
    const int kk4 = tid & 3, cbase = tid >> 2;
    for (int k0 = 0; k0 < EE; k0 += 16) {
        __syncthreads();
#pragma unroll
        for (int q = 0; q < 4; q++) {
            const int c = cbase + 64 * q;
            float4 v = *reinterpret_cast<const float4*>(W_ih + (size_t)c * EE + k0 + kk4 * 4);
            Wt[kk4 * 4 + 0][c] = v.x; Wt[kk4 * 4 + 1][c] = v.y;
            Wt[kk4 * 4 + 2][c] = v.z; Wt[kk4 * 4 + 3][c] = v.w;
        }
        __syncthreads();
#pragma unroll
        for (int kk = 0; kk < 16; kk++) {
            float a[4];
#pragma unroll
            for (int i = 0; i < 4; i++) a[i] = Asm[r_t * 4 + i][k0 + kk];
            float w[8];
            *reinterpret_cast<float4*>(w)     = *reinterpret_cast<const float4*>(&Wt[kk][c_t * 8]);
            *reinterpret_cast<float4*>(w + 4) = *reinterpret_cast<const float4*>(&Wt[kk][c_t * 8 + 4]);
#pragma unroll
            for (int i = 0; i < 4; i++)
#pragma unroll
                for (int j = 0; j < 8; j++) acc[i][j] += a[i] * w[j];
        }
    }
#pragma unroll
    for (int i = 0; i < 4; i++) {
        const int v = b0 + r_t * 4 + i;
        if (v < VV) {
            float* dst = g_embw + (size_t)v * HH + c_t * 8;
            *reinterpret_cast<float4*>(dst)     = *reinterpret_cast<float4*>(&acc[i][0]);
            *reinterpret_cast<float4*>(dst + 4) = *reinterpret_cast<float4*>(&acc[i][4]);
        }
    }
}

// ---------------------------------------------------------------------------
// RNN scan with mma.sync (bf16 3-term split).
// grid 128 x 256 thr. dyn smem: Whi 128K | h_hi 16K | h_lo 16K = 160 KB
// ---------------------------------------------------------------------------
__global__ __launch_bounds__(NTHREADS, 1) void rnn_mma_kernel(
    const int* __restrict__ x_in, const int* __restrict__ x_lengths)
{
    extern __shared__ __align__(16) unsigned char dsm[];
    __shared__ int s_xi[SS * 32];
    __shared__ int s_len[32];

    const int tid = threadIdx.x;
    const int w = tid >> 5, l = tid & 31;
    const int b0 = blockIdx.x * 32;
    const uint32_t base = smem_u32(dsm);
    const uint32_t sWhi = base, sHhi = base + 131072, sHlo = base + 147456;

    for (int i = tid; i < 8192; i += NTHREADS)
        reinterpret_cast<uint4*>(dsm)[i] = reinterpret_cast<const uint4*>(g_whi16)[i];
    for (int i = tid; i < 8192; i += NTHREADS)
        reinterpret_cast<uint32_t*>(dsm + 131072)[i] = 0;   // h_hi + h_lo = 32KB
    for (int i = tid; i < SS * 32; i += NTHREADS) {
        int v = x_in[b0 * SS + i];
        s_xi[(i & 63) * 32 + (i >> 6)] = v;
    }
    if (tid < 32) s_len[tid] = x_lengths[b0 + tid];
    __syncthreads();

    const int lq = l & 15, lh = l >> 4;
    const uint32_t sxor = (uint32_t)(l & 7) << 4;
    uint32_t aHi[2], aLo[2], bHi[2];
#pragma unroll
    for (int mi = 0; mi < 2; mi++) {
        aHi[mi] = sHhi + (mi * 16 + lq) * 512;
        aLo[mi] = sHlo + (mi * 16 + lq) * 512;
        bHi[mi] = sWhi + (w * 32 + mi * 16 + lq) * 512;
    }
    int wbase[4];
#pragma unroll
    for (int nj = 0; nj < 4; nj++)
        wbase[nj] = (w * 32 + nj * 8 + (l >> 2)) * 128 + (l & 3);

    for (int t = 0; t < SS; t++) {
        float acc[2][4][4];
#pragma unroll
        for (int mi = 0; mi < 2; mi++)
#pragma unroll
            for (int nj = 0; nj < 4; nj++)
#pragma unroll
                for (int c = 0; c < 4; c++) acc[mi][nj][c] = 0.0f;

#pragma unroll
        for (int k16 = 0; k16 < 16; k16++) {
            const uint32_t koff = (uint32_t)((k16 * 32) | (lh * 16)) ^ sxor;
            uint32_t Ah[2][4], Al[2][4], Bh[2][4], Bl[4][2];
            ldm4(Ah[0], aHi[0] + koff); ldm4(Ah[1], aHi[1] + koff);
            ldm4(Al[0], aLo[0] + koff); ldm4(Al[1], aLo[1] + koff);
            ldm4(Bh[0], bHi[0] + koff); ldm4(Bh[1], bHi[1] + koff);
#pragma unroll
            for (int nj = 0; nj < 4; nj++) {
                Bl[nj][0] = g_wlo32[wbase[nj] + k16 * 8];
                Bl[nj][1] = g_wlo32[wbase[nj] + k16 * 8 + 4];
            }
#pragma unroll
            for (int mi = 0; mi < 2; mi++)
#pragma unroll
                for (int nj = 0; nj < 4; nj++) {
                    const uint32_t b0r = Bh[nj >> 1][nj & 1];
                    const uint32_t b1r = Bh[nj >> 1][(nj & 1) + 2];
                    mma16816(acc[mi][nj], Ah[mi], b0r, b1r);
                    mma16816(acc[mi][nj], Al[mi], b0r, b1r);
                    mma16816(acc[mi][nj], Ah[mi], Bl[nj][0], Bl[nj][1]);
                }
        }
        __syncthreads();   // all reads of h done before overwrite

#pragma unroll
        for (int mi = 0; mi < 2; mi++)
#pragma unroll
            for (int h8 = 0; h8 < 2; h8++) {
                const int r = mi * 16 + h8 * 8 + (l >> 2);
                const int idx = s_xi[t * 32 + r];
                const float2* e2 = reinterpret_cast<const float2*>(g_embw + (size_t)idx * HH);
                const bool save = (t == s_len[r] - 1);
                float2* lastp = reinterpret_cast<float2*>(g_last + (size_t)(b0 + r) * HH);
                const uint32_t rxor = (uint32_t)(r & 7) << 4;
#pragma unroll
                for (int nj = 0; nj < 4; nj++) {
                    const int ei = w * 16 + nj * 4 + (l & 3);
                    float2 e = e2[ei];
                    float v0 = fast_tanh(acc[mi][nj][h8 * 2]     + e.x);
                    float v1 = fast_tanh(acc[mi][nj][h8 * 2 + 1] + e.y);
                    __nv_bfloat162 hh = __float22bfloat162_rn(make_float2(v0, v1));
                    float f0 = __bfloat162float(__low2bfloat16(hh));
                    float f1 = __bfloat162float(__high2bfloat16(hh));
                    __nv_bfloat162 ll = __float22bfloat162_rn(make_float2(v0 - f0, v1 - f1));
                    const uint32_t cb = ((uint32_t)(w * 64 + nj * 16 + (l & 3) * 4)) ^ rxor;
                    *reinterpret_cast<uint32_t*>(dsm + 131072 + r * 512 + cb) =
                        *reinterpret_cast<uint32_t*>(&hh);
                    *reinterpret_cast<uint32_t*>(dsm + 147456 + r * 512 + cb) =
                        *reinterpret_cast<uint32_t*>(&ll);
                    if (save) lastp[ei] = make_float2(v0, v1);
                }
            }
        __syncthreads();
    }
}

// ---------------------------------------------------------------------------
// FC head
// ---------------------------------------------------------------------------
__global__ __launch_bounds__(NTHREADS) void fc_kernel(
    const float* __restrict__ W1, const float* __restrict__ b1,
    const float* __restrict__ W2, const float* __restrict__ b2,
    float* __restrict__ out)
{
    __shared__ float Asm[32][HH];
    __shared__ float Wt[16][HH];
    const int b0 = blockIdx.x * 32;
    const int tid = threadIdx.x;
    const int r_t = tid >> 5, c_t = tid & 31;

    for (int i = tid; i < 32 * HH; i += NTHREADS)
        (&Asm[0][0])[i] = g_last[(size_t)b0 * HH + i];

    float acc[4][8];
    {
        float4 bl = *reinterpret_cast<const float4*>(b1 + c_t * 8);
        float4 bh = *reinterpret_cast<const float4*>(b1 + c_t * 8 + 4);
        float bias[8] = {bl.x, bl.y, bl.z, bl.w, bh.x, bh.y, bh.z, bh.w};
#pragma unroll
        for (int i = 0; i < 4; i++)
#pragma unroll
            for (int j = 0; j < 8; j++) acc[i][j] = bias[j];
    }
    const int kk4 = tid & 3, cbase = tid >> 2;
    for (int k0 = 0; k0 < HH; k0 += 16) {
        __syncthreads();
#pragma unroll
        for (int q = 0; q < 4; q++) {
            const int c = cbase + 64 * q;
            float4 v = *reinterpret_cast<const float4*>(W1 + (size_t)c * HH + k0 + kk4 * 4);
            Wt[kk4 * 4 + 0][c] = v.x; Wt[kk4 * 4 + 1][c] = v.y;
            Wt[kk4 * 4 + 2][c] = v.z; Wt[kk4 * 4 + 3][c] = v.w;
        }
        __syncthreads();
#pragma unroll
        for (int kk = 0; kk < 16; kk++) {
            float a[4];
#pragma unroll
            for (int i = 0; i < 4; i++) a[i] = Asm[r_t * 4 + i][k0 + kk];
            float w[8];
            *reinterpret_cast<float4*>(w)     = *reinterpret_cast<const float4*>(&Wt[kk][c_t * 8]);
            *reinterpret_cast<float4*>(w + 4) = *reinterpret_cast<const float4*>(&Wt[kk][c_t * 8 + 4]);
#pragma unroll
            for (int i = 0; i < 4; i++)
#pragma unroll
                for (int j = 0; j < 8; j++) acc[i][j] += a[i] * w[j];
        }
    }
    __syncthreads();
#pragma unroll
    for (int i = 0; i < 4; i++) {
        float yv[8];
#pragma unroll
        for (int j = 0; j < 8; j++) yv[j] = fmaxf(acc[i][j], 0.0f);
        float* yd = &Asm[r_t * 4 + i][c_t * 8];
        *reinterpret_cast<float4*>(yd)     = *reinterpret_cast<float4*>(&yv[0]);
        *reinterpret_cast<float4*>(yd + 4) = *reinterpret_cast<float4*>(&yv[4]);
    }
    __syncthreads();
    for (int e = tid; e < 32 * CC; e += NTHREADS) {
        const int r = e / CC, c = e % CC;
        const float4* yv = reinterpret_cast<const float4*>(&Asm[r][0]);
        const float4* wv = reinterpret_cast<const float4*>(W2 + (size_t)c * HH);
        float s = b2[c];
#pragma unroll 8
        for (int k = 0; k < HH / 4; k++) {
            float4 a = yv[k]; float4 wq = wv[k];
            s += a.x * wq.x + a.y * wq.y + a.z * wq.z + a.w * wq.w;
        }
        out[(size_t)(b0 + r) * CC + c] = s;
    }
}

// ---------------------------------------------------------------------------
extern "C" void kernel_launch(void* const* d_in, const int* in_sizes, int n_in,
                              void* d_out, int out_size)
{
    const int*   x_in  = (const int*)  d_in[0];
    const int*   x_len = (const int*)  d_in[1];
    const float* emb   = (const float*)d_in[2];
    const float* W_ih  = (const float*)d_in[3];
    const float* W_hh  = (const float*)d_in[4];
    const float* b_ih  = (const float*)d_in[5];
    const float* b_hh  = (const float*)d_in[6];
    const float* W1    = (const float*)d_in[7];
    const float* b1    = (const float*)d_in[8];
    const float* W2    = (const float*)d_in[9];
    const float* b2    = (const float*)d_in[10];
    float* out = (float*)d_out;

    const int DSM = 131072 + 32768;   // Whi + h_hi + h_lo
    cudaFuncSetAttribute(rnn_mma_kernel, cudaFuncAttributeMaxDynamicSharedMemorySize, DSM);

    prep_w_kernel<<<256, NTHREADS>>>(W_hh);
    embw_kernel<<<(VV + 31) / 32, NTHREADS>>>(emb, W_ih, b_ih, b_hh);
    rnn_mma_kernel<<<BB / 32, NTHREADS, DSM>>>(x_in, x_len);
    fc_kernel<<<BB / 32, NTHREADS>>>(W1, b1, W2, b2, out);
}

// round 8
// speedup vs baseline: 3.4580x; 1.2950x over previous
#include <cuda_runtime.h>
#include <cuda_bf16.h>
#include <cstdint>

#define VV 10000
#define BB 4096
#define SS 64
#define EE 128
#define HH 256
#define CC 18
#define NTHREADS 256

__device__ __align__(16) float    g_embw[VV * HH];
__device__ __align__(16) float    g_last[BB * HH];
__device__ __align__(16) uint16_t g_whi16[HH * HH];     // W_hh bf16-hi, swizzled SMEM image
__device__ __align__(16) uint32_t g_wlo32[HH * HH / 2]; // W_hh bf16-lo packed words

__device__ __forceinline__ float fast_tanh(float x) {
    float e = __expf(2.0f * x);
    return 1.0f - __fdividef(2.0f, e + 1.0f);
}
__device__ __forceinline__ uint32_t smem_u32(const void* p) {
    uint32_t a;
    asm("{ .reg .u64 t; cvta.to.shared.u64 t, %1; cvt.u32.u64 %0, t; }" : "=r"(a) : "l"(p));
    return a;
}
__device__ __forceinline__ void ldm4(uint32_t* d, uint32_t a) {
    asm volatile("ldmatrix.sync.aligned.m8n8.x4.shared.b16 {%0,%1,%2,%3}, [%4];"
                 : "=r"(d[0]), "=r"(d[1]), "=r"(d[2]), "=r"(d[3]) : "r"(a));
}
__device__ __forceinline__ void mma16816(float* c, const uint32_t* a, uint32_t b0, uint32_t b1) {
    asm volatile("mma.sync.aligned.m16n8k16.row.col.f32.bf16.bf16.f32 "
                 "{%0,%1,%2,%3}, {%4,%5,%6,%7}, {%8,%9}, {%0,%1,%2,%3};"
                 : "+f"(c[0]), "+f"(c[1]), "+f"(c[2]), "+f"(c[3])
                 : "r"(a[0]), "r"(a[1]), "r"(a[2]), "r"(a[3]), "r"(b0), "r"(b1));
}

// ---------------------------------------------------------------------------
__global__ __launch_bounds__(NTHREADS) void prep_w_kernel(const float* __restrict__ W)
{
    const int i = blockIdx.x * NTHREADS + threadIdx.x;    // 0..65535
    const int n = i >> 8, k = i & 255;
    const float w = W[i];
    __nv_bfloat16 h = __float2bfloat16(w);
    __nv_bfloat16 l = __float2bfloat16(w - __bfloat162float(h));
    g_whi16[n * 256 + (k ^ ((n & 7) << 3))] = *reinterpret_cast<uint16_t*>(&h);
    reinterpret_cast<uint16_t*>(g_wlo32)[n * 256 + k] = *reinterpret_cast<uint16_t*>(&l);
}

// ---------------------------------------------------------------------------
__global__ __launch_bounds__(NTHREADS) void embw_kernel(
    const float* __restrict__ emb, const float* __restrict__ W_ih,
    const float* __restrict__ b_ih, const float* __restrict__ b_hh)
{
    __shared__ float Asm[32][EE];
    __shared__ float Wt[16][HH];
    const int b0 = blockIdx.x * 32;
    const int tid = threadIdx.x;
    {
        const int r = tid >> 3, seg = tid & 7;
        int v = b0 + r; if (v >= VV) v = VV - 1;
        const float4* src = reinterpret_cast<const float4*>(emb + (size_t)v * EE + seg * 16);
        float4* dst = reinterpret_cast<float4*>(&Asm[r][seg * 16]);
#pragma unroll
        for (int q = 0; q < 4; q++) dst[q] = src[q];
    }
    const int r_t = tid >> 5, c_t = tid & 31;
    float acc[4][8];
    {
        float bias[8];
#pragma unroll
        for (int j = 0; j < 8; j++) bias[j] = b_ih[c_t * 8 + j] + b_hh[c_t * 8 + j];
#pragma unroll
        for (int i = 0; i < 4; i++)
#pragma unroll
            for (int j = 0; j < 8; j++) acc[i][j] = bias[j];
    }
    const int kk4 = tid & 3, cbase = tid >> 2;
    for (int k0 = 0; k0 < EE; k0 += 16) {
        __syncthreads();
#pragma unroll
        for (int q = 0; q < 4; q++) {
            const int c = cbase + 64 * q;
            float4 v = *reinterpret_cast<const float4*>(W_ih + (size_t)c * EE + k0 + kk4 * 4);
            Wt[kk4 * 4 + 0][c] = v.x; Wt[kk4 * 4 + 1][c] = v.y;
            Wt[kk4 * 4 + 2][c] = v.z; Wt[kk4 * 4 + 3][c] = v.w;
        }
        __syncthreads();
#pragma unroll
        for (int kk = 0; kk < 16; kk++) {
            float a[4];
#pragma unroll
            for (int i = 0; i < 4; i++) a[i] = Asm[r_t * 4 + i][k0 + kk];
            float w[8];
            *reinterpret_cast<float4*>(w)     = *reinterpret_cast<const float4*>(&Wt[kk][c_t * 8]);
            *reinterpret_cast<float4*>(w + 4) = *reinterpret_cast<const float4*>(&Wt[kk][c_t * 8 + 4]);
#pragma unroll
            for (int i = 0; i < 4; i++)
#pragma unroll
                for (int j = 0; j < 8; j++) acc[i][j] += a[i] * w[j];
        }
    }
#pragma unroll
    for (int i = 0; i < 4; i++) {
        const int v = b0 + r_t * 4 + i;
        if (v < VV) {
            float* dst = g_embw + (size_t)v * HH + c_t * 8;
            *reinterpret_cast<float4*>(dst)     = *reinterpret_cast<float4*>(&acc[i][0]);
            *reinterpret_cast<float4*>(dst + 4) = *reinterpret_cast<float4*>(&acc[i][4]);
        }
    }
}

// ---------------------------------------------------------------------------
// RNN scan, mma.sync bf16 3-term split, double-buffered h, prefetched gathers.
// dyn smem: Whi 128K | h buffers 2x(hi16K+lo16K) = 192 KB
// ---------------------------------------------------------------------------
__global__ __launch_bounds__(NTHREADS, 1) void rnn_mma_kernel(
    const int* __restrict__ x_in, const int* __restrict__ x_lengths)
{
    extern __shared__ __align__(16) unsigned char dsm[];
    __shared__ int s_xi[SS * 32];
    __shared__ int s_len[32];

    const int tid = threadIdx.x;
    const int w = tid >> 5, l = tid & 31;
    const int b0 = blockIdx.x * 32;
    const uint32_t base = smem_u32(dsm);
    const uint32_t sWhi = base;

    for (int i = tid; i < 8192; i += NTHREADS)
        reinterpret_cast<uint4*>(dsm)[i] = reinterpret_cast<const uint4*>(g_whi16)[i];
    for (int i = tid; i < 8192; i += NTHREADS)
        reinterpret_cast<uint32_t*>(dsm + 131072)[i] = 0;   // zero h buffer 0 (hi+lo)
    for (int i = tid; i < SS * 32; i += NTHREADS)
        s_xi[(i & 63) * 32 + (i >> 6)] = x_in[b0 * SS + i];
    if (tid < 32) s_len[tid] = x_lengths[b0 + tid];
    __syncthreads();

    const int lq = l & 15, lh = l >> 4;
    const uint32_t sxor = (uint32_t)(l & 7) << 4;
    uint32_t bHi[2];
#pragma unroll
    for (int mi = 0; mi < 2; mi++)
        bHi[mi] = sWhi + (w * 32 + mi * 16 + lq) * 512;
    int wbase[4];
#pragma unroll
    for (int nj = 0; nj < 4; nj++)
        wbase[nj] = (w * 32 + nj * 8 + (l >> 2)) * 128 + (l & 3);

    for (int t = 0; t < SS; t++) {
        const uint32_t rb = 131072u + (uint32_t)(t & 1) * 32768u;      // read buf
        const uint32_t wb = 131072u + (uint32_t)((t + 1) & 1) * 32768u; // write buf

        // ---- prefetch epilogue inputs (hidden behind MMA) ----
        float2 ev[4][4];
        int rr[4]; bool sv[4];
#pragma unroll
        for (int cb = 0; cb < 4; cb++) {
            const int r = (cb >> 1) * 16 + (cb & 1) * 8 + (l >> 2);
            rr[cb] = r;
            const int idx = s_xi[t * 32 + r];
            sv[cb] = (t == s_len[r] - 1);
            const float2* e2 = reinterpret_cast<const float2*>(g_embw + (size_t)idx * HH);
#pragma unroll
            for (int nj = 0; nj < 4; nj++)
                ev[cb][nj] = e2[w * 16 + nj * 4 + (l & 3)];
        }

        float acc[2][4][4];
#pragma unroll
        for (int mi = 0; mi < 2; mi++)
#pragma unroll
            for (int nj = 0; nj < 4; nj++)
#pragma unroll
                for (int c = 0; c < 4; c++) acc[mi][nj][c] = 0.0f;

        // W_lo pipeline: preload k16=0
        uint32_t Blp[2][8];
#pragma unroll
        for (int nj = 0; nj < 4; nj++) {
            Blp[0][nj * 2]     = g_wlo32[wbase[nj]];
            Blp[0][nj * 2 + 1] = g_wlo32[wbase[nj] + 4];
        }

#pragma unroll
        for (int k16 = 0; k16 < 16; k16++) {
            if (k16 < 15) {
#pragma unroll
                for (int nj = 0; nj < 4; nj++) {
                    Blp[(k16 + 1) & 1][nj * 2]     = g_wlo32[wbase[nj] + (k16 + 1) * 8];
                    Blp[(k16 + 1) & 1][nj * 2 + 1] = g_wlo32[wbase[nj] + (k16 + 1) * 8 + 4];
                }
            }
            const uint32_t* Bl = Blp[k16 & 1];
            const uint32_t koff = (uint32_t)((k16 * 32) | (lh * 16)) ^ sxor;
            uint32_t Ah[2][4], Al[2][4], Bh[2][4];
            ldm4(Ah[0], base + rb + lq * 512 + koff);
            ldm4(Ah[1], base + rb + (16 + lq) * 512 + koff);
            ldm4(Al[0], base + rb + 16384 + lq * 512 + koff);
            ldm4(Al[1], base + rb + 16384 + (16 + lq) * 512 + koff);
            ldm4(Bh[0], bHi[0] + koff);
            ldm4(Bh[1], bHi[1] + koff);
#pragma unroll
            for (int mi = 0; mi < 2; mi++)
#pragma unroll
                for (int nj = 0; nj < 4; nj++) {
                    const uint32_t b0r = Bh[nj >> 1][nj & 1];
                    const uint32_t b1r = Bh[nj >> 1][(nj & 1) + 2];
                    mma16816(acc[mi][nj], Ah[mi], b0r, b1r);
                    mma16816(acc[mi][nj], Al[mi], b0r, b1r);
                    mma16816(acc[mi][nj], Ah[mi], Bl[nj * 2], Bl[nj * 2 + 1]);
                }
        }

        // ---- epilogue: tanh, split, write to OTHER h buffer ----
#pragma unroll
        for (int cb = 0; cb < 4; cb++) {
            const int mi = cb >> 1, h8 = cb & 1;
            const int r = rr[cb];
            float2* lastp = reinterpret_cast<float2*>(g_last + (size_t)(b0 + r) * HH);
            const uint32_t rxor = (uint32_t)(r & 7) << 4;
#pragma unroll
            for (int nj = 0; nj < 4; nj++) {
                float v0 = fast_tanh(acc[mi][nj][h8 * 2]     + ev[cb][nj].x);
                float v1 = fast_tanh(acc[mi][nj][h8 * 2 + 1] + ev[cb][nj].y);
                __nv_bfloat162 hh = __float22bfloat162_rn(make_float2(v0, v1));
                float f0 = __bfloat162float(__low2bfloat16(hh));
                float f1 = __bfloat162float(__high2bfloat16(hh));
                __nv_bfloat162 ll = __float22bfloat162_rn(make_float2(v0 - f0, v1 - f1));
                const uint32_t cbo = ((uint32_t)(w * 64 + nj * 16 + (l & 3) * 4)) ^ rxor;
                *reinterpret_cast<uint32_t*>(dsm + wb + r * 512 + cbo) =
                    *reinterpret_cast<uint32_t*>(&hh);
                *reinterpret_cast<uint32_t*>(dsm + wb + 16384 + r * 512 + cbo) =
                    *reinterpret_cast<uint32_t*>(&ll);
                if (sv[cb]) lastp[w * 16 + nj * 4 + (l & 3)] = make_float2(v0, v1);
            }
        }
        __syncthreads();
    }
}

// ---------------------------------------------------------------------------
// FC head, BM=16, grid 256
// ---------------------------------------------------------------------------
#define BMF 16
__global__ __launch_bounds__(NTHREADS) void fc_kernel(
    const float* __restrict__ W1, const float* __restrict__ b1,
    const float* __restrict__ W2, const float* __restrict__ b2,
    float* __restrict__ out)
{
    __shared__ float Asm[BMF][HH];
    __shared__ float Wt[16][HH];
    const int b0 = blockIdx.x * BMF;
    const int tid = threadIdx.x;
    const int r_t = tid >> 5, c_t = tid & 31;

    for (int i = tid; i < BMF * HH; i += NTHREADS)
        (&Asm[0][0])[i] = g_last[(size_t)b0 * HH + i];

    float acc[2][8];
    {
        float4 bl = *reinterpret_cast<const float4*>(b1 + c_t * 8);
        float4 bh = *reinterpret_cast<const float4*>(b1 + c_t * 8 + 4);
        float bias[8] = {bl.x, bl.y, bl.z, bl.w, bh.x, bh.y, bh.z, bh.w};
#pragma unroll
        for (int i = 0; i < 2; i++)
#pragma unroll
            for (int j = 0; j < 8; j++) acc[i][j] = bias[j];
    }
    const int kk4 = tid & 3, cbase = tid >> 2;
    for (int k0 = 0; k0 < HH; k0 += 16) {
        __syncthreads();
#pragma unroll
        for (int q = 0; q < 4; q++) {
            const int c = cbase + 64 * q;
            float4 v = *reinterpret_cast<const float4*>(W1 + (size_t)c * HH + k0 + kk4 * 4);
            Wt[kk4 * 4 + 0][c] = v.x; Wt[kk4 * 4 + 1][c] = v.y;
            Wt[kk4 * 4 + 2][c] = v.z; Wt[kk4 * 4 + 3][c] = v.w;
        }
        __syncthreads();
#pragma unroll
        for (int kk = 0; kk < 16; kk++) {
            float a[2];
#pragma unroll
            for (int i = 0; i < 2; i++) a[i] = Asm[r_t * 2 + i][k0 + kk];
            float w[8];
            *reinterpret_cast<float4*>(w)     = *reinterpret_cast<const float4*>(&Wt[kk][c_t * 8]);
            *reinterpret_cast<float4*>(w + 4) = *reinterpret_cast<const float4*>(&Wt[kk][c_t * 8 + 4]);
#pragma unroll
            for (int i = 0; i < 2; i++)
#pragma unroll
                for (int j = 0; j < 8; j++) acc[i][j] += a[i] * w[j];
        }
    }
    __syncthreads();
#pragma unroll
    for (int i = 0; i < 2; i++) {
        float yv[8];
#pragma unroll
        for (int j = 0; j < 8; j++) yv[j] = fmaxf(acc[i][j], 0.0f);
        float* yd = &Asm[r_t * 2 + i][c_t * 8];
        *reinterpret_cast<float4*>(yd)     = *reinterpret_cast<float4*>(&yv[0]);
        *reinterpret_cast<float4*>(yd + 4) = *reinterpret_cast<float4*>(&yv[4]);
    }
    __syncthreads();
    for (int e = tid; e < BMF * CC; e += NTHREADS) {
        const int r = e / CC, c = e % CC;
        const float4* yv = reinterpret_cast<const float4*>(&Asm[r][0]);
        const float4* wv = reinterpret_cast<const float4*>(W2 + (size_t)c * HH);
        float s = b2[c];
#pragma unroll 8
        for (int k = 0; k < HH / 4; k++) {
            float4 a = yv[k]; float4 wq = wv[k];
            s += a.x * wq.x + a.y * wq.y + a.z * wq.z + a.w * wq.w;
        }
        out[(size_t)(b0 + r) * CC + c] = s;
    }
}

// ---------------------------------------------------------------------------
extern "C" void kernel_launch(void* const* d_in, const int* in_sizes, int n_in,
                              void* d_out, int out_size)
{
    const int*   x_in  = (const int*)  d_in[0];
    const int*   x_len = (const int*)  d_in[1];
    const float* emb   = (const float*)d_in[2];
    const float* W_ih  = (const float*)d_in[3];
    const float* W_hh  = (const float*)d_in[4];
    const float* b_ih  = (const float*)d_in[5];
    const float* b_hh  = (const float*)d_in[6];
    const float* W1    = (const float*)d_in[7];
    const float* b1    = (const float*)d_in[8];
    const float* W2    = (const float*)d_in[9];
    const float* b2    = (const float*)d_in[10];
    float* out = (float*)d_out;

    const int DSM = 131072 + 65536;   // Whi + 2x(h_hi+h_lo)
    cudaFuncSetAttribute(rnn_mma_kernel, cudaFuncAttributeMaxDynamicSharedMemorySize, DSM);

    prep_w_kernel<<<256, NTHREADS>>>(W_hh);
    embw_kernel<<<(VV + 31) / 32, NTHREADS>>>(emb, W_ih, b_ih, b_hh);
    rnn_mma_kernel<<<BB / 32, NTHREADS, DSM>>>(x_in, x_len);
    fc_kernel<<<BB / BMF, NTHREADS>>>(W1, b1, W2, b2, out);
}

// round 9
// speedup vs baseline: 5.8000x; 1.6773x over previous
#include <cuda_runtime.h>
#include <cuda_fp16.h>
#include <cstdint>

#define VV 10000
#define BB 4096
#define SS 64
#define EE 128
#define HH 256
#define CC 18
#define NTHREADS 256

__device__ __align__(16) float    g_embw[VV * HH];
__device__ __align__(16) float    g_last[BB * HH];
__device__ __align__(16) uint16_t g_whi16[HH * HH];   // W_hh fp16, swizzled SMEM image

__device__ __forceinline__ float fast_tanh(float x) {
    float e = __expf(2.0f * x);
    return 1.0f - __fdividef(2.0f, e + 1.0f);
}
__device__ __forceinline__ uint32_t smem_u32(const void* p) {
    uint32_t a;
    asm("{ .reg .u64 t; cvta.to.shared.u64 t, %1; cvt.u32.u64 %0, t; }" : "=r"(a) : "l"(p));
    return a;
}
__device__ __forceinline__ void ldm4(uint32_t* d, uint32_t a) {
    asm volatile("ldmatrix.sync.aligned.m8n8.x4.shared.b16 {%0,%1,%2,%3}, [%4];"
                 : "=r"(d[0]), "=r"(d[1]), "=r"(d[2]), "=r"(d[3]) : "r"(a));
}
__device__ __forceinline__ void mma16816(float* c, const uint32_t* a, uint32_t b0, uint32_t b1) {
    asm volatile("mma.sync.aligned.m16n8k16.row.col.f32.f16.f16.f32 "
                 "{%0,%1,%2,%3}, {%4,%5,%6,%7}, {%8,%9}, {%0,%1,%2,%3};"
                 : "+f"(c[0]), "+f"(c[1]), "+f"(c[2]), "+f"(c[3])
                 : "r"(a[0]), "r"(a[1]), "r"(a[2]), "r"(a[3]), "r"(b0), "r"(b1));
}

// ---------------------------------------------------------------------------
__global__ __launch_bounds__(NTHREADS) void prep_w_kernel(const float* __restrict__ W)
{
    const int i = blockIdx.x * NTHREADS + threadIdx.x;    // 0..65535
    const int n = i >> 8, k = i & 255;
    __half h = __float2half_rn(W[i]);
    g_whi16[n * 256 + (k ^ ((n & 7) << 3))] = *reinterpret_cast<uint16_t*>(&h);
}

// ---------------------------------------------------------------------------
__global__ __launch_bounds__(NTHREADS) void embw_kernel(
    const float* __restrict__ emb, const float* __restrict__ W_ih,
    const float* __restrict__ b_ih, const float* __restrict__ b_hh)
{
    __shared__ float Asm[32][EE];
    __shared__ float Wt[16][HH];
    const int b0 = blockIdx.x * 32;
    const int tid = threadIdx.x;
    {
        const int r = tid >> 3, seg = tid & 7;
        int v = b0 + r; if (v >= VV) v = VV - 1;
        const float4* src = reinterpret_cast<const float4*>(emb + (size_t)v * EE + seg * 16);
        float4* dst = reinterpret_cast<float4*>(&Asm[r][seg * 16]);
#pragma unroll
        for (int q = 0; q < 4; q++) dst[q] = src[q];
    }
    const int r_t = tid >> 5, c_t = tid & 31;
    float acc[4][8];
    {
        float bias[8];
#pragma unroll
        for (int j = 0; j < 8; j++) bias[j] = b_ih[c_t * 8 + j] + b_hh[c_t * 8 + j];
#pragma unroll
        for (int i = 0; i < 4; i++)
#pragma unroll
            for (int j = 0; j < 8; j++) acc[i][j] = bias[j];
    }
    const int kk4 = tid & 3, cbase = tid >> 2;
    for (int k0 = 0; k0 < EE; k0 += 16) {
        __syncthreads();
#pragma unroll
        for (int q = 0; q < 4; q++) {
            const int c = cbase + 64 * q;
            float4 v = *reinterpret_cast<const float4*>(W_ih + (size_t)c * EE + k0 + kk4 * 4);
            Wt[kk4 * 4 + 0][c] = v.x; Wt[kk4 * 4 + 1][c] = v.y;
            Wt[kk4 * 4 + 2][c] = v.z; Wt[kk4 * 4 + 3][c] = v.w;
        }
        __syncthreads();
#pragma unroll
        for (int kk = 0; kk < 16; kk++) {
            float a[4];
#pragma unroll
            for (int i = 0; i < 4; i++) a[i] = Asm[r_t * 4 + i][k0 + kk];
            float w[8];
            *reinterpret_cast<float4*>(w)     = *reinterpret_cast<const float4*>(&Wt[kk][c_t * 8]);
            *reinterpret_cast<float4*>(w + 4) = *reinterpret_cast<const float4*>(&Wt[kk][c_t * 8 + 4]);
#pragma unroll
            for (int i = 0; i < 4; i++)
#pragma unroll
                for (int j = 0; j < 8; j++) acc[i][j] += a[i] * w[j];
        }
    }
#pragma unroll
    for (int i = 0; i < 4; i++) {
        const int v = b0 + r_t * 4 + i;
        if (v < VV) {
            float* dst = g_embw + (size_t)v * HH + c_t * 8;
            *reinterpret_cast<float4*>(dst)     = *reinterpret_cast<float4*>(&acc[i][0]);
            *reinterpret_cast<float4*>(dst + 4) = *reinterpret_cast<float4*>(&acc[i][4]);
        }
    }
}

// ---------------------------------------------------------------------------
// RNN scan: mma.sync fp16 2-term split (A=hi+lo fp16, W=fp16).
// dyn smem: Whi 128K | h buffers 2x(hi16K+lo16K) = 192 KB
// ---------------------------------------------------------------------------
__global__ __launch_bounds__(NTHREADS, 1) void rnn_mma_kernel(
    const int* __restrict__ x_in, const int* __restrict__ x_lengths)
{
    extern __shared__ __align__(16) unsigned char dsm[];
    __shared__ int s_xi[SS * 32];
    __shared__ int s_len[32];

    const int tid = threadIdx.x;
    const int w = tid >> 5, l = tid & 31;
    const int b0 = blockIdx.x * 32;
    const uint32_t base = smem_u32(dsm);

    for (int i = tid; i < 8192; i += NTHREADS)
        reinterpret_cast<uint4*>(dsm)[i] = reinterpret_cast<const uint4*>(g_whi16)[i];
    for (int i = tid; i < 8192; i += NTHREADS)
        reinterpret_cast<uint32_t*>(dsm + 131072)[i] = 0;   // zero h buffer 0 (hi+lo)
    for (int i = tid; i < SS * 32; i += NTHREADS)
        s_xi[(i & 63) * 32 + (i >> 6)] = x_in[b0 * SS + i];
    if (tid < 32) s_len[tid] = x_lengths[b0 + tid];
    __syncthreads();

    const int lq = l & 15, lh = l >> 4;
    const uint32_t sxor = (uint32_t)(l & 7) << 4;
    uint32_t bHi[2];
#pragma unroll
    for (int mi = 0; mi < 2; mi++)
        bHi[mi] = base + (w * 32 + mi * 16 + lq) * 512;

    for (int t = 0; t < SS; t++) {
        const uint32_t rb = 131072u + (uint32_t)(t & 1) * 32768u;       // read buf
        const uint32_t wb = 131072u + (uint32_t)((t + 1) & 1) * 32768u; // write buf

        // prefetch epilogue inputs (hidden behind MMA)
        float2 ev[4][4];
        int rr[4]; bool sv[4];
#pragma unroll
        for (int cb = 0; cb < 4; cb++) {
            const int r = (cb >> 1) * 16 + (cb & 1) * 8 + (l >> 2);
            rr[cb] = r;
            const int idx = s_xi[t * 32 + r];
            sv[cb] = (t == s_len[r] - 1);
            const float2* e2 = reinterpret_cast<const float2*>(g_embw + (size_t)idx * HH);
#pragma unroll
            for (int nj = 0; nj < 4; nj++)
                ev[cb][nj] = e2[w * 16 + nj * 4 + (l & 3)];
        }

        float acc[2][4][4];
#pragma unroll
        for (int mi = 0; mi < 2; mi++)
#pragma unroll
            for (int nj = 0; nj < 4; nj++)
#pragma unroll
                for (int c = 0; c < 4; c++) acc[mi][nj][c] = 0.0f;

#pragma unroll
        for (int k16 = 0; k16 < 16; k16++) {
            const uint32_t koff = (uint32_t)((k16 * 32) | (lh * 16)) ^ sxor;
            uint32_t Ah[2][4], Al[2][4], Bh[2][4];
            ldm4(Ah[0], base + rb + lq * 512 + koff);
            ldm4(Ah[1], base + rb + (16 + lq) * 512 + koff);
            ldm4(Al[0], base + rb + 16384 + lq * 512 + koff);
            ldm4(Al[1], base + rb + 16384 + (16 + lq) * 512 + koff);
            ldm4(Bh[0], bHi[0] + koff);
            ldm4(Bh[1], bHi[1] + koff);
#pragma unroll
            for (int mi = 0; mi < 2; mi++)
#pragma unroll
                for (int nj = 0; nj < 4; nj++) {
                    const uint32_t b0r = Bh[nj >> 1][nj & 1];
                    const uint32_t b1r = Bh[nj >> 1][(nj & 1) + 2];
                    mma16816(acc[mi][nj], Ah[mi], b0r, b1r);
                    mma16816(acc[mi][nj], Al[mi], b0r, b1r);
                }
        }

        // epilogue: tanh, fp16 hi/lo split, write to OTHER h buffer
#pragma unroll
        for (int cb = 0; cb < 4; cb++) {
            const int mi = cb >> 1, h8 = cb & 1;
            const int r = rr[cb];
            float2* lastp = reinterpret_cast<float2*>(g_last + (size_t)(b0 + r) * HH);
            const uint32_t rxor = (uint32_t)(r & 7) << 4;
#pragma unroll
            for (int nj = 0; nj < 4; nj++) {
                float v0 = fast_tanh(acc[mi][nj][h8 * 2]     + ev[cb][nj].x);
                float v1 = fast_tanh(acc[mi][nj][h8 * 2 + 1] + ev[cb][nj].y);
                __half2 hh = __floats2half2_rn(v0, v1);
                float f0 = __half2float(__low2half(hh));
                float f1 = __half2float(__high2half(hh));
                __half2 ll = __floats2half2_rn(v0 - f0, v1 - f1);
                const uint32_t cbo = ((uint32_t)(w * 64 + nj * 16 + (l & 3) * 4)) ^ rxor;
                *reinterpret_cast<uint32_t*>(dsm + wb + r * 512 + cbo) =
                    *reinterpret_cast<uint32_t*>(&hh);
                *reinterpret_cast<uint32_t*>(dsm + wb + 16384 + r * 512 + cbo) =
                    *reinterpret_cast<uint32_t*>(&ll);
                if (sv[cb]) lastp[w * 16 + nj * 4 + (l & 3)] = make_float2(v0, v1);
            }
        }
        __syncthreads();
    }
}

// ---------------------------------------------------------------------------
// FC head, BM=32, grid 128, single-sync double-buffered W tiles
// ---------------------------------------------------------------------------
__global__ __launch_bounds__(NTHREADS) void fc_kernel(
    const float* __restrict__ W1, const float* __restrict__ b1,
    const float* __restrict__ W2, const float* __restrict__ b2,
    float* __restrict__ out)
{
    __shared__ float Asm[32][HH];
    __shared__ float Wt[2][16][HH];
    const int b0 = blockIdx.x * 32;
    const int tid = threadIdx.x;
    const int r_t = tid >> 5, c_t = tid & 31;
    const int kk4 = tid & 3, cbase = tid >> 2;

    for (int i = tid; i < 32 * HH; i += NTHREADS)
        (&Asm[0][0])[i] = g_last[(size_t)b0 * HH + i];

    float acc[4][8];
    {
        float4 bl = *reinterpret_cast<const float4*>(b1 + c_t * 8);
        float4 bh = *reinterpret_cast<const float4*>(b1 + c_t * 8 + 4);
        float bias[8] = {bl.x, bl.y, bl.z, bl.w, bh.x, bh.y, bh.z, bh.w};
#pragma unroll
        for (int i = 0; i < 4; i++)
#pragma unroll
            for (int j = 0; j < 8; j++) acc[i][j] = bias[j];
    }

    // preload tile 0
    float4 pf[4];
#pragma unroll
    for (int q = 0; q < 4; q++)
        pf[q] = *reinterpret_cast<const float4*>(W1 + (size_t)(cbase + 64 * q) * HH + kk4 * 4);
#pragma unroll
    for (int q = 0; q < 4; q++) {
        const int c = cbase + 64 * q;
        Wt[0][kk4 * 4 + 0][c] = pf[q].x; Wt[0][kk4 * 4 + 1][c] = pf[q].y;
        Wt[0][kk4 * 4 + 2][c] = pf[q].z; Wt[0][kk4 * 4 + 3][c] = pf[q].w;
    }
    __syncthreads();

    for (int kt = 0; kt < 16; kt++) {
        if (kt < 15) {
#pragma unroll
            for (int q = 0; q < 4; q++)
                pf[q] = *reinterpret_cast<const float4*>(
                    W1 + (size_t)(cbase + 64 * q) * HH + (kt + 1) * 16 + kk4 * 4);
        }
        const float (*Wb)[HH] = Wt[kt & 1];
#pragma unroll
        for (int kk = 0; kk < 16; kk++) {
            float a[4];
#pragma unroll
            for (int i = 0; i < 4; i++) a[i] = Asm[r_t * 4 + i][kt * 16 + kk];
            float w[8];
            *reinterpret_cast<float4*>(w)     = *reinterpret_cast<const float4*>(&Wb[kk][c_t * 8]);
            *reinterpret_cast<float4*>(w + 4) = *reinterpret_cast<const float4*>(&Wb[kk][c_t * 8 + 4]);
#pragma unroll
            for (int i = 0; i < 4; i++)
#pragma unroll
                for (int j = 0; j < 8; j++) acc[i][j] += a[i] * w[j];
        }
        if (kt < 15) {
            float (*Wd)[HH] = Wt[(kt + 1) & 1];
#pragma unroll
            for (int q = 0; q < 4; q++) {
                const int c = cbase + 64 * q;
                Wd[kk4 * 4 + 0][c] = pf[q].x; Wd[kk4 * 4 + 1][c] = pf[q].y;
                Wd[kk4 * 4 + 2][c] = pf[q].z; Wd[kk4 * 4 + 3][c] = pf[q].w;
            }
        }
        __syncthreads();
    }

#pragma unroll
    for (int i = 0; i < 4; i++) {
        float yv[8];
#pragma unroll
        for (int j = 0; j < 8; j++) yv[j] = fmaxf(acc[i][j], 0.0f);
        float* yd = &Asm[r_t * 4 + i][c_t * 8];
        *reinterpret_cast<float4*>(yd)     = *reinterpret_cast<float4*>(&yv[0]);
        *reinterpret_cast<float4*>(yd + 4) = *reinterpret_cast<float4*>(&yv[4]);
    }
    __syncthreads();
    for (int e = tid; e < 32 * CC; e += NTHREADS) {
        const int r = e / CC, c = e % CC;
        const float4* yv = reinterpret_cast<const float4*>(&Asm[r][0]);
        const float4* wv = reinterpret_cast<const float4*>(W2 + (size_t)c * HH);
        float s = b2[c];
#pragma unroll 8
        for (int k = 0; k < HH / 4; k++) {
            float4 a = yv[k]; float4 wq = wv[k];
            s += a.x * wq.x + a.y * wq.y + a.z * wq.z + a.w * wq.w;
        }
        out[(size_t)(b0 + r) * CC + c] = s;
    }
}

// ---------------------------------------------------------------------------
extern "C" void kernel_launch(void* const* d_in, const int* in_sizes, int n_in,
                              void* d_out, int out_size)
{
    const int*   x_in  = (const int*)  d_in[0];
    const int*   x_len = (const int*)  d_in[1];
    const float* emb   = (const float*)d_in[2];
    const float* W_ih  = (const float*)d_in[3];
    const float* W_hh  = (const float*)d_in[4];
    const float* b_ih  = (const float*)d_in[5];
    const float* b_hh  = (const float*)d_in[6];
    const float* W1    = (const float*)d_in[7];
    const float* b1    = (const float*)d_in[8];
    const float* W2    = (const float*)d_in[9];
    const float* b2    = (const float*)d_in[10];
    float* out = (float*)d_out;

    const int DSM = 131072 + 65536;   // Whi + 2x(h_hi+h_lo)
    cudaFuncSetAttribute(rnn_mma_kernel, cudaFuncAttributeMaxDynamicSharedMemorySize, DSM);

    prep_w_kernel<<<256, NTHREADS>>>(W_hh);
    embw_kernel<<<(VV + 31) / 32, NTHREADS>>>(emb, W_ih, b_ih, b_hh);
    rnn_mma_kernel<<<BB / 32, NTHREADS, DSM>>>(x_in, x_len);
    fc_kernel<<<BB / 32, NTHREADS>>>(W1, b1, W2, b2, out);
}

// round 10
// speedup vs baseline: 7.6077x; 1.3117x over previous
#include <cuda_runtime.h>
#include <cuda_fp16.h>
#include <cstdint>

#define VV 10000
#define BB 4096
#define SS 64
#define EE 128
#define HH 256
#define CC 18
#define NTHREADS 256

__device__ __align__(16) float    g_embw[VV * HH];
__device__ __align__(16) float    g_last[BB * HH];
__device__ __align__(16) uint16_t g_whi16[HH * HH];   // W_hh fp16, swizzled SMEM image

__device__ __forceinline__ float fast_tanh(float x) {
    float e = __expf(2.0f * x);
    return 1.0f - __fdividef(2.0f, e + 1.0f);
}
__device__ __forceinline__ uint32_t smem_u32(const void* p) {
    uint32_t a;
    asm("{ .reg .u64 t; cvta.to.shared.u64 t, %1; cvt.u32.u64 %0, t; }" : "=r"(a) : "l"(p));
    return a;
}
__device__ __forceinline__ void ldm4(uint32_t* d, uint32_t a) {
    asm volatile("ldmatrix.sync.aligned.m8n8.x4.shared.b16 {%0,%1,%2,%3}, [%4];"
                 : "=r"(d[0]), "=r"(d[1]), "=r"(d[2]), "=r"(d[3]) : "r"(a));
}
__device__ __forceinline__ void mma16816(float* c, const uint32_t* a, uint32_t b0, uint32_t b1) {
    asm volatile("mma.sync.aligned.m16n8k16.row.col.f32.f16.f16.f32 "
                 "{%0,%1,%2,%3}, {%4,%5,%6,%7}, {%8,%9}, {%0,%1,%2,%3};"
                 : "+f"(c[0]), "+f"(c[1]), "+f"(c[2]), "+f"(c[3])
                 : "r"(a[0]), "r"(a[1]), "r"(a[2]), "r"(a[3]), "r"(b0), "r"(b1));
}

// ---------------------------------------------------------------------------
__global__ __launch_bounds__(NTHREADS) void prep_w_kernel(const float* __restrict__ W)
{
    const int i = blockIdx.x * NTHREADS + threadIdx.x;    // 0..65535
    const int n = i >> 8, k = i & 255;
    __half h = __float2half_rn(W[i]);
    g_whi16[n * 256 + (k ^ ((n & 7) << 3))] = *reinterpret_cast<uint16_t*>(&h);
}

// ---------------------------------------------------------------------------
__global__ __launch_bounds__(NTHREADS) void embw_kernel(
    const float* __restrict__ emb, const float* __restrict__ W_ih,
    const float* __restrict__ b_ih, const float* __restrict__ b_hh)
{
    __shared__ float Asm[32][EE];
    __shared__ float Wt[16][HH];
    const int b0 = blockIdx.x * 32;
    const int tid = threadIdx.x;
    {
        const int r = tid >> 3, seg = tid & 7;
        int v = b0 + r; if (v >= VV) v = VV - 1;
        const float4* src = reinterpret_cast<const float4*>(emb + (size_t)v * EE + seg * 16);
        float4* dst = reinterpret_cast<float4*>(&Asm[r][seg * 16]);
#pragma unroll
        for (int q = 0; q < 4; q++) dst[q] = src[q];
    }
    const int r_t = tid >> 5, c_t = tid & 31;
    float acc[4][8];
    {
        float bias[8];
#pragma unroll
        for (int j = 0; j < 8; j++) bias[j] = b_ih[c_t * 8 + j] + b_hh[c_t * 8 + j];
#pragma unroll
        for (int i = 0; i < 4; i++)
#pragma unroll
            for (int j = 0; j < 8; j++) acc[i][j] = bias[j];
    }
    const int kk4 = tid & 3, cbase = tid >> 2;
    for (int k0 = 0; k0 < EE; k0 += 16) {
        __syncthreads();
#pragma unroll
        for (int q = 0; q < 4; q++) {
            const int c = cbase + 64 * q;
            float4 v = *reinterpret_cast<const float4*>(W_ih + (size_t)c * EE + k0 + kk4 * 4);
            Wt[kk4 * 4 + 0][c] = v.x; Wt[kk4 * 4 + 1][c] = v.y;
            Wt[kk4 * 4 + 2][c] = v.z; Wt[kk4 * 4 + 3][c] = v.w;
        }
        __syncthreads();
#pragma unroll
        for (int kk = 0; kk < 16; kk++) {
            float a[4];
#pragma unroll
            for (int i = 0; i < 4; i++) a[i] = Asm[r_t * 4 + i][k0 + kk];
            float w[8];
            *reinterpret_cast<float4*>(w)     = *reinterpret_cast<const float4*>(&Wt[kk][c_t * 8]);
            *reinterpret_cast<float4*>(w + 4) = *reinterpret_cast<const float4*>(&Wt[kk][c_t * 8 + 4]);
#pragma unroll
            for (int i = 0; i < 4; i++)
#pragma unroll
                for (int j = 0; j < 8; j++) acc[i][j] += a[i] * w[j];
        }
    }
#pragma unroll
    for (int i = 0; i < 4; i++) {
        const int v = b0 + r_t * 4 + i;
        if (v < VV) {
            float* dst = g_embw + (size_t)v * HH + c_t * 8;
            *reinterpret_cast<float4*>(dst)     = *reinterpret_cast<float4*>(&acc[i][0]);
            *reinterpret_cast<float4*>(dst + 4) = *reinterpret_cast<float4*>(&acc[i][4]);
        }
    }
}

// ---------------------------------------------------------------------------
// RNN scan: mma.sync fp16 single-term (A fp16, W fp16, f32 accum).
// dyn smem: Whi 128K | h buffers 2x16K = 160 KB
// ---------------------------------------------------------------------------
__global__ __launch_bounds__(NTHREADS, 1) void rnn_mma_kernel(
    const int* __restrict__ x_in, const int* __restrict__ x_lengths)
{
    extern __shared__ __align__(16) unsigned char dsm[];
    __shared__ int s_xi[SS * 32];
    __shared__ int s_len[32];

    const int tid = threadIdx.x;
    const int w = tid >> 5, l = tid & 31;
    const int b0 = blockIdx.x * 32;
    const uint32_t base = smem_u32(dsm);

    for (int i = tid; i < 8192; i += NTHREADS)
        reinterpret_cast<uint4*>(dsm)[i] = reinterpret_cast<const uint4*>(g_whi16)[i];
    for (int i = tid; i < 4096; i += NTHREADS)
        reinterpret_cast<uint32_t*>(dsm + 131072)[i] = 0;   // zero h buffer 0
    for (int i = tid; i < SS * 32; i += NTHREADS)
        s_xi[(i & 63) * 32 + (i >> 6)] = x_in[b0 * SS + i];
    if (tid < 32) s_len[tid] = x_lengths[b0 + tid];
    __syncthreads();

    const int lq = l & 15, lh = l >> 4;
    const uint32_t sxor = (uint32_t)(l & 7) << 4;
    uint32_t bHi[2];
#pragma unroll
    for (int mi = 0; mi < 2; mi++)
        bHi[mi] = base + (w * 32 + mi * 16 + lq) * 512;

    for (int t = 0; t < SS; t++) {
        const uint32_t rb = 131072u + (uint32_t)(t & 1) * 16384u;       // read buf
        const uint32_t wb = 131072u + (uint32_t)((t + 1) & 1) * 16384u; // write buf

        // prefetch epilogue inputs (hidden behind MMA)
        float2 ev[4][4];
        int rr[4]; bool sv[4];
#pragma unroll
        for (int cb = 0; cb < 4; cb++) {
            const int r = (cb >> 1) * 16 + (cb & 1) * 8 + (l >> 2);
            rr[cb] = r;
            const int idx = s_xi[t * 32 + r];
            sv[cb] = (t == s_len[r] - 1);
            const float2* e2 = reinterpret_cast<const float2*>(g_embw + (size_t)idx * HH);
#pragma unroll
            for (int nj = 0; nj < 4; nj++)
                ev[cb][nj] = e2[w * 16 + nj * 4 + (l & 3)];
        }

        float acc[2][4][4];
#pragma unroll
        for (int mi = 0; mi < 2; mi++)
#pragma unroll
            for (int nj = 0; nj < 4; nj++)
#pragma unroll
                for (int c = 0; c < 4; c++) acc[mi][nj][c] = 0.0f;

#pragma unroll
        for (int k16 = 0; k16 < 16; k16++) {
            const uint32_t koff = (uint32_t)((k16 * 32) | (lh * 16)) ^ sxor;
            uint32_t Ah[2][4], Bh[2][4];
            ldm4(Ah[0], base + rb + lq * 512 + koff);
            ldm4(Ah[1], base + rb + (16 + lq) * 512 + koff);
            ldm4(Bh[0], bHi[0] + koff);
            ldm4(Bh[1], bHi[1] + koff);
#pragma unroll
            for (int mi = 0; mi < 2; mi++)
#pragma unroll
                for (int nj = 0; nj < 4; nj++) {
                    const uint32_t b0r = Bh[nj >> 1][nj & 1];
                    const uint32_t b1r = Bh[nj >> 1][(nj & 1) + 2];
                    mma16816(acc[mi][nj], Ah[mi], b0r, b1r);
                }
        }

        // epilogue: tanh, fp16 round, write to OTHER h buffer
#pragma unroll
        for (int cb = 0; cb < 4; cb++) {
            const int mi = cb >> 1, h8 = cb & 1;
            const int r = rr[cb];
            float2* lastp = reinterpret_cast<float2*>(g_last + (size_t)(b0 + r) * HH);
            const uint32_t rxor = (uint32_t)(r & 7) << 4;
#pragma unroll
            for (int nj = 0; nj < 4; nj++) {
                float v0 = fast_tanh(acc[mi][nj][h8 * 2]     + ev[cb][nj].x);
                float v1 = fast_tanh(acc[mi][nj][h8 * 2 + 1] + ev[cb][nj].y);
                __half2 hh = __floats2half2_rn(v0, v1);
                const uint32_t cbo = ((uint32_t)(w * 64 + nj * 16 + (l & 3) * 4)) ^ rxor;
                *reinterpret_cast<uint32_t*>(dsm + wb + r * 512 + cbo) =
                    *reinterpret_cast<uint32_t*>(&hh);
                if (sv[cb]) lastp[w * 16 + nj * 4 + (l & 3)] = make_float2(v0, v1);
            }
        }
        __syncthreads();
    }
}

// ---------------------------------------------------------------------------
// FC head, BM=32, grid 128, single-sync double-buffered W tiles
// ---------------------------------------------------------------------------
__global__ __launch_bounds__(NTHREADS) void fc_kernel(
    const float* __restrict__ W1, const float* __restrict__ b1,
    const float* __restrict__ W2, const float* __restrict__ b2,
    float* __restrict__ out)
{
    __shared__ float Asm[32][HH];
    __shared__ float Wt[2][16][HH];
    const int b0 = blockIdx.x * 32;
    const int tid = threadIdx.x;
    const int r_t = tid >> 5, c_t = tid & 31;
    const int kk4 = tid & 3, cbase = tid >> 2;

    for (int i = tid; i < 32 * HH; i += NTHREADS)
        (&Asm[0][0])[i] = g_last[(size_t)b0 * HH + i];

    float acc[4][8];
    {
        float4 bl = *reinterpret_cast<const float4*>(b1 + c_t * 8);
        float4 bh = *reinterpret_cast<const float4*>(b1 + c_t * 8 + 4);
        float bias[8] = {bl.x, bl.y, bl.z, bl.w, bh.x, bh.y, bh.z, bh.w};
#pragma unroll
        for (int i = 0; i < 4; i++)
#pragma unroll
            for (int j = 0; j < 8; j++) acc[i][j] = bias[j];
    }

    float4 pf[4];
#pragma unroll
    for (int q = 0; q < 4; q++)
        pf[q] = *reinterpret_cast<const float4*>(W1 + (size_t)(cbase + 64 * q) * HH + kk4 * 4);
#pragma unroll
    for (int q = 0; q < 4; q++) {
        const int c = cbase + 64 * q;
        Wt[0][kk4 * 4 + 0][c] = pf[q].x; Wt[0][kk4 * 4 + 1][c] = pf[q].y;
        Wt[0][kk4 * 4 + 2][c] = pf[q].z; Wt[0][kk4 * 4 + 3][c] = pf[q].w;
    }
    __syncthreads();

    for (int kt = 0; kt < 16; kt++) {
        if (kt < 15) {
#pragma unroll
            for (int q = 0; q < 4; q++)
                pf[q] = *reinterpret_cast<const float4*>(
                    W1 + (size_t)(cbase + 64 * q) * HH + (kt + 1) * 16 + kk4 * 4);
        }
        const float (*Wb)[HH] = Wt[kt & 1];
#pragma unroll
        for (int kk = 0; kk < 16; kk++) {
            float a[4];
#pragma unroll
            for (int i = 0; i < 4; i++) a[i] = Asm[r_t * 4 + i][kt * 16 + kk];
            float w[8];
            *reinterpret_cast<float4*>(w)     = *reinterpret_cast<const float4*>(&Wb[kk][c_t * 8]);
            *reinterpret_cast<float4*>(w + 4) = *reinterpret_cast<const float4*>(&Wb[kk][c_t * 8 + 4]);
#pragma unroll
            for (int i = 0; i < 4; i++)
#pragma unroll
                for (int j = 0; j < 8; j++) acc[i][j] += a[i] * w[j];
        }
        if (kt < 15) {
            float (*Wd)[HH] = Wt[(kt + 1) & 1];
#pragma unroll
            for (int q = 0; q < 4; q++) {
                const int c = cbase + 64 * q;
                Wd[kk4 * 4 + 0][c] = pf[q].x; Wd[kk4 * 4 + 1][c] = pf[q].y;
                Wd[kk4 * 4 + 2][c] = pf[q].z; Wd[kk4 * 4 + 3][c] = pf[q].w;
            }
        }
        __syncthreads();
    }

#pragma unroll
    for (int i = 0; i < 4; i++) {
        float yv[8];
#pragma unroll
        for (int j = 0; j < 8; j++) yv[j] = fmaxf(acc[i][j], 0.0f);
        float* yd = &Asm[r_t * 4 + i][c_t * 8];
        *reinterpret_cast<float4*>(yd)     = *reinterpret_cast<float4*>(&yv[0]);
        *reinterpret_cast<float4*>(yd + 4) = *reinterpret_cast<float4*>(&yv[4]);
    }
    __syncthreads();
    for (int e = tid; e < 32 * CC; e += NTHREADS) {
        const int r = e / CC, c = e % CC;
        const float4* yv = reinterpret_cast<const float4*>(&Asm[r][0]);
        const float4* wv = reinterpret_cast<const float4*>(W2 + (size_t)c * HH);
        float s = b2[c];
#pragma unroll 8
        for (int k = 0; k < HH / 4; k++) {
            float4 a = yv[k]; float4 wq = wv[k];
            s += a.x * wq.x + a.y * wq.y + a.z * wq.z + a.w * wq.w;
        }
        out[(size_t)(b0 + r) * CC + c] = s;
    }
}

// ---------------------------------------------------------------------------
extern "C" void kernel_launch(void* const* d_in, const int* in_sizes, int n_in,
                              void* d_out, int out_size)
{
    const int*   x_in  = (const int*)  d_in[0];
    const int*   x_len = (const int*)  d_in[1];
    const float* emb   = (const float*)d_in[2];
    const float* W_ih  = (const float*)d_in[3];
    const float* W_hh  = (const float*)d_in[4];
    const float* b_ih  = (const float*)d_in[5];
    const float* b_hh  = (const float*)d_in[6];
    const float* W1    = (const float*)d_in[7];
    const float* b1    = (const float*)d_in[8];
    const float* W2    = (const float*)d_in[9];
    const float* b2    = (const float*)d_in[10];
    float* out = (float*)d_out;

    const int DSM = 131072 + 32768;   // Whi + 2x h_hi
    cudaFuncSetAttribute(rnn_mma_kernel, cudaFuncAttributeMaxDynamicSharedMemorySize, DSM);

    prep_w_kernel<<<256, NTHREADS>>>(W_hh);
    embw_kernel<<<(VV + 31) / 32, NTHREADS>>>(emb, W_ih, b_ih, b_hh);
    rnn_mma_kernel<<<BB / 32, NTHREADS, DSM>>>(x_in, x_len);
    fc_kernel<<<BB / 32, NTHREADS>>>(W1, b1, W2, b2, out);
}